// round 2
// baseline (speedup 1.0000x reference)
#include <cuda_runtime.h>
#include <math.h>

// Problem geometry (fixed by the dataset):
//   x: [16, 4, 2048, 257] fp32  ->  BM = 64 series-groups, T = 2048, F = 257
#define BM_     64
#define T_      2048
#define F_      257
#define NCHUNK  32          // T chunks per series
#define CLEN    64          // frames per chunk (NCHUNK * CLEN == T_)
#define NTHREADS 288        // 9 warps; threads [0,257) active (one per f)
#define EPS_    1e-6f

// Scratch: published EMA tail per (bm, chunk, f). Poisoned to -1 each launch;
// every legal value is >= 0 (x is uniform[0,1)), so the value itself is the flag.
__device__ float        g_mend[BM_ * NCHUNK * F_];
__device__ unsigned int g_ticket;

__global__ void pcen_reset_kernel() {
    int n = BM_ * NCHUNK * F_;
    int i = blockIdx.x * blockDim.x + threadIdx.x;
    if (i == 0) g_ticket = 0u;
    for (; i < n; i += gridDim.x * blockDim.x) g_mend[i] = -1.0f;
}

__device__ __forceinline__ float ld_relaxed_gpu(const float* p) {
    float v;
    asm volatile("ld.relaxed.gpu.f32 %0, [%1];" : "=f"(v) : "l"(p));
    return v;
}
__device__ __forceinline__ void st_relaxed_gpu(float* p, float v) {
    asm volatile("st.relaxed.gpu.f32 [%0], %1;" :: "l"(p), "f"(v));
}

__global__ __launch_bounds__(NTHREADS, 2)
void pcen_kernel(const float* __restrict__ x,
                 const float* __restrict__ s_p,
                 const float* __restrict__ alpha_p,
                 const float* __restrict__ delta_p,
                 const float* __restrict__ r_p,
                 float* __restrict__ out) {
    // Ticket-order virtualization: a block's role is decided by arrival order,
    // so a waiter's predecessor (ticket - 64) is guaranteed resident or done.
    __shared__ unsigned int s_vb;
    if (threadIdx.x == 0) s_vb = atomicAdd(&g_ticket, 1u);
    __syncthreads();
    const unsigned int vb = s_vb;
    const int bm = (int)(vb & (BM_ - 1));   // fast-varying: all bm chains advance per wave
    const int c  = (int)(vb >> 6);          // chunk index along T

    const int f = threadIdx.x;
    if (f >= F_) return;

    const float s     = s_p[0];
    const float alpha = alpha_p[0];
    const float delta = delta_p[0];
    const float r     = r_p[0];
    const float oms   = 1.0f - s;

    const size_t base = ((size_t)bm * T_ + (size_t)c * CLEN) * F_ + f;
    const float* xp = x + base;

    // ---- Phase 0: stream chunk into registers (coalesced 128B rows across f) ----
    float xr[CLEN];
#pragma unroll
    for (int i = 0; i < CLEN; i++) xr[i] = xp[(size_t)i * F_];

    // ---- Phase 1: local EMA with zero initial state (chunk 0: m_0 = x_0) ----
    float m;
    if (c == 0) {
        m = xr[0];
#pragma unroll
        for (int i = 1; i < CLEN; i++) m = fmaf(oms, m, s * xr[i]);
    } else {
        m = s * xr[0];
#pragma unroll
        for (int i = 1; i < CLEN; i++) m = fmaf(oms, m, s * xr[i]);
    }

    // ---- Phase 2: chain combine. Per-f spin on predecessor's published tail. ----
    float m_in = 0.0f;
    if (c > 0) {
        float D = oms;                        // (1-s)^64 by repeated squaring
#pragma unroll
        for (int k = 0; k < 6; k++) D *= D;
        const float* prev = &g_mend[((size_t)bm * NCHUNK + (size_t)(c - 1)) * F_ + f];
        float v;
        do { v = ld_relaxed_gpu(prev); } while (v < 0.0f);
        m_in = v;
        m = fmaf(D, m_in, m);                 // exact-to-rounding linear combine
    }
    // Publish ASAP to unblock the successor chunk.
    st_relaxed_gpu(&g_mend[((size_t)bm * NCHUNK + (size_t)c) * F_ + f], m);

    // ---- Phase 3: replay exact recurrence from m_in, emit PCEN output ----
    const bool half = (r == 0.5f);
    const float dr  = half ? sqrtf(delta) : exp2f(r * __log2f(delta));

    float* op = out + base;
    float mm = (c == 0) ? xr[0] : fmaf(oms, m_in, s * xr[0]);
#pragma unroll
    for (int i = 0; i < CLEN; i++) {
        if (i > 0) mm = fmaf(oms, mm, s * xr[i]);
        // (x / (mm+eps)^alpha + delta)^r - delta^r
        const float pw = exp2f(-alpha * __log2f(mm + EPS_));
        const float u  = fmaf(xr[i], pw, delta);
        const float o  = half ? (sqrtf(u) - dr)
                              : (exp2f(r * __log2f(u)) - dr);
        op[(size_t)i * F_] = o;
    }
}

extern "C" void kernel_launch(void* const* d_in, const int* in_sizes, int n_in,
                              void* d_out, int out_size) {
    const float* x     = (const float*)d_in[0];
    const float* s     = (const float*)d_in[1];
    const float* alpha = (const float*)d_in[2];
    const float* delta = (const float*)d_in[3];
    const float* r     = (const float*)d_in[4];
    float* out = (float*)d_out;

    (void)in_sizes; (void)n_in; (void)out_size;

    pcen_reset_kernel<<<512, 256>>>();                 // re-poison scratch + ticket
    pcen_kernel<<<BM_ * NCHUNK, NTHREADS>>>(x, s, alpha, delta, r, out);
}